// round 3
// baseline (speedup 1.0000x reference)
#include <cuda_runtime.h>

// loss = sum_{rows, j>=1} relu(|x[:,j]-x[:,j-1]|-1) * mask[:,j]
// x, mask: [65536, 512] fp32. HBM streaming reduction: 256 MB read, 4 B out.
//
// Each thread handles 8 contiguous floats per iteration (2 float4 of x, 2 of
// mask, 1 scalar prev). No shfl: all 5 loads per iteration are independent,
// letting ptxas pipeline loads across iterations without warp-wide barriers.

#define THREADS   256
#define BLOCKS    1024
#define ITERS     16            // 33554432 floats / (1024*256*8) == 16 exactly
#define ROW_MASK  511

__device__ float        g_partials[BLOCKS];
__device__ unsigned int g_ticket = 0;   // zero-init; reset by last block each run

__global__ __launch_bounds__(THREADS)
void connect_loss_kernel(const float* __restrict__ x,
                         const float* __restrict__ mask,
                         float* __restrict__ out) {
    const float4* __restrict__ x4 = reinterpret_cast<const float4*>(x);
    const float4* __restrict__ m4 = reinterpret_cast<const float4*>(mask);

    const long long tid = (long long)blockIdx.x * THREADS + threadIdx.x;
    // per-iteration stride in floats = 1024*256*8 = 2097152, a multiple of 512,
    // so the row-position of this thread's chunk is loop-invariant.
    const bool rowstart = ((tid * 8) & ROW_MASK) == 0;

    float s = 0.0f;
    long long c = tid;                       // chunk index (8 floats per chunk)
    const long long cstride = (long long)BLOCKS * THREADS;

    #pragma unroll 4
    for (int it = 0; it < ITERS; ++it, c += cstride) {
        const long long f4 = c * 2;          // float4 index
        const long long f  = c * 8;          // float index

        float4 a  = __ldcs(x4 + f4);
        float4 b  = __ldcs(x4 + f4 + 1);
        float4 ma = __ldcs(m4 + f4);
        float4 mb = __ldcs(m4 + f4 + 1);
        float prev = rowstart ? 0.0f : __ldcs(x + f - 1);

        float acc;
        float d0 = fmaxf(fabsf(a.x - prev) - 1.0f, 0.0f) * ma.x;
        acc  = rowstart ? 0.0f : d0;
        acc += fmaxf(fabsf(a.y - a.x) - 1.0f, 0.0f) * ma.y;
        acc += fmaxf(fabsf(a.z - a.y) - 1.0f, 0.0f) * ma.z;
        acc += fmaxf(fabsf(a.w - a.z) - 1.0f, 0.0f) * ma.w;
        acc += fmaxf(fabsf(b.x - a.w) - 1.0f, 0.0f) * mb.x;
        acc += fmaxf(fabsf(b.y - b.x) - 1.0f, 0.0f) * mb.y;
        acc += fmaxf(fabsf(b.z - b.y) - 1.0f, 0.0f) * mb.z;
        acc += fmaxf(fabsf(b.w - b.z) - 1.0f, 0.0f) * mb.w;
        s += acc;
    }

    // ---- block reduction ----
    __shared__ float smem[THREADS / 32];
    __shared__ bool  amLast;
    const int lane = threadIdx.x & 31;
    const int w    = threadIdx.x >> 5;

    #pragma unroll
    for (int o = 16; o > 0; o >>= 1)
        s += __shfl_xor_sync(0xffffffffu, s, o);

    if (lane == 0) smem[w] = s;
    __syncthreads();

    if (threadIdx.x == 0) {
        float bs = 0.0f;
        #pragma unroll
        for (int k = 0; k < THREADS / 32; ++k) bs += smem[k];
        g_partials[blockIdx.x] = bs;
        __threadfence();
        unsigned int t = atomicAdd(&g_ticket, 1u);
        amLast = (t == BLOCKS - 1);
    }
    __syncthreads();

    // ---- last block: deterministic final reduction over 1024 partials ----
    if (amLast) {
        __threadfence();
        float v = 0.0f;
        #pragma unroll
        for (int k = 0; k < BLOCKS / THREADS; ++k)
            v += g_partials[threadIdx.x + k * THREADS];

        #pragma unroll
        for (int o = 16; o > 0; o >>= 1)
            v += __shfl_xor_sync(0xffffffffu, v, o);

        if (lane == 0) smem[w] = v;
        __syncthreads();

        if (threadIdx.x == 0) {
            float total = 0.0f;
            #pragma unroll
            for (int k = 0; k < THREADS / 32; ++k) total += smem[k];
            out[0] = total;
            g_ticket = 0;     // reset for next graph replay
        }
    }
}

extern "C" void kernel_launch(void* const* d_in, const int* in_sizes, int n_in,
                              void* d_out, int out_size) {
    const float* x    = (const float*)d_in[0];
    const float* mask = (const float*)d_in[1];
    float* out = (float*)d_out;

    connect_loss_kernel<<<BLOCKS, THREADS>>>(x, mask, out);
}

// round 6
// speedup vs baseline: 1.0855x; 1.0855x over previous
#include <cuda_runtime.h>

// loss = sum_{rows, j>=1} relu(|x[:,j]-x[:,j-1]|-1) * mask[:,j]
// x, mask: [65536, 512] fp32. 256 MB HBM streaming reduction.
//
// Warp-per-row layout: each warp owns 8 complete rows. Lane l reads float4
// 32*j + l of the row (j=0..3). prev element comes from shfl_up within the
// chunk and a register carry (lane 31's v.w) across chunks. No scalar loads,
// no divergent branches, warp reads are 2KB-contiguous per row.

#define THREADS       256
#define BLOCKS        1024            // single wave; 8192 warps
#define WARPS         (BLOCKS * THREADS / 32)
#define ROWS_PER_WARP 8               // 65536 rows / 8192 warps
#define ROW_F4        128             // float4s per 512-float row

__device__ float        g_partials[BLOCKS];
__device__ unsigned int g_ticket = 0;   // zero-init; reset by last block each run

__global__ __launch_bounds__(THREADS)
void connect_loss_kernel(const float* __restrict__ x,
                         const float* __restrict__ mask,
                         float* __restrict__ out) {
    const float4* __restrict__ x4 = reinterpret_cast<const float4*>(x);
    const float4* __restrict__ m4 = reinterpret_cast<const float4*>(mask);

    const int lane = threadIdx.x & 31;
    const int gw   = blockIdx.x * (THREADS / 32) + (threadIdx.x >> 5);

    float acc = 0.0f;

    for (int rr = 0; rr < ROWS_PER_WARP; ++rr) {
        const long long row  = (long long)gw * ROWS_PER_WARP + rr;
        const long long base = row * ROW_F4;

        float carry = 0.0f;   // x element just before this chunk (reg-carried)

        #pragma unroll
        for (int j = 0; j < 4; ++j) {
            float4 v = x4[base + j * 32 + lane];
            float4 m = m4[base + j * 32 + lane];

            float prev = __shfl_up_sync(0xffffffffu, v.w, 1);
            if (lane == 0) prev = carry;
            carry = __shfl_sync(0xffffffffu, v.w, 31);

            float t0 = fmaxf(fabsf(v.x - prev) - 1.0f, 0.0f) * m.x;
            if (j == 0 && lane == 0) t0 = 0.0f;      // column 0 contributes 0
            float a = t0;
            a += fmaxf(fabsf(v.y - v.x) - 1.0f, 0.0f) * m.y;
            a += fmaxf(fabsf(v.z - v.y) - 1.0f, 0.0f) * m.z;
            a += fmaxf(fabsf(v.w - v.z) - 1.0f, 0.0f) * m.w;
            acc += a;
        }
    }

    // ---- block reduction ----
    __shared__ float red[THREADS / 32];
    __shared__ bool  amLast;
    const int w = threadIdx.x >> 5;

    #pragma unroll
    for (int o = 16; o > 0; o >>= 1)
        acc += __shfl_xor_sync(0xffffffffu, acc, o);

    if (lane == 0) red[w] = acc;
    __syncthreads();

    if (threadIdx.x == 0) {
        float bs = 0.0f;
        #pragma unroll
        for (int i = 0; i < THREADS / 32; ++i) bs += red[i];
        g_partials[blockIdx.x] = bs;
        __threadfence();
        unsigned int t = atomicAdd(&g_ticket, 1u);
        amLast = (t == BLOCKS - 1);
    }
    __syncthreads();

    // ---- last block: deterministic final reduction over 1024 partials ----
    if (amLast) {
        __threadfence();
        float v = 0.0f;
        #pragma unroll
        for (int k = 0; k < BLOCKS / THREADS; ++k)
            v += g_partials[threadIdx.x + k * THREADS];

        #pragma unroll
        for (int o = 16; o > 0; o >>= 1)
            v += __shfl_xor_sync(0xffffffffu, v, o);

        if (lane == 0) red[w] = v;
        __syncthreads();

        if (threadIdx.x == 0) {
            float total = 0.0f;
            #pragma unroll
            for (int i = 0; i < THREADS / 32; ++i) total += red[i];
            out[0] = total;
            g_ticket = 0;   // reset for next graph replay
        }
    }
}

extern "C" void kernel_launch(void* const* d_in, const int* in_sizes, int n_in,
                              void* d_out, int out_size) {
    const float* x    = (const float*)d_in[0];
    const float* mask = (const float*)d_in[1];
    float* out = (float*)d_out;

    connect_loss_kernel<<<BLOCKS, THREADS>>>(x, mask, out);
}